// round 16
// baseline (speedup 1.0000x reference)
#include <cuda_runtime.h>
#include <cuda_fp16.h>
#include <cstdint>
#include <mma.h>

using namespace nvcuda;

#define N_NODES 50000
#define N_EDGES 800000
#define D_MODEL 128
// heads = 8, head_dim = 16

#define SCAN_BLK 256
#define SCAN_NBLK ((N_NODES + SCAN_BLK - 1) / SCAN_BLK)   // 196

#define TILE_M 128
#define N_TILES ((N_NODES + TILE_M - 1) / TILE_M)         // 391
#define PAD_NODES (N_TILES * TILE_M)                      // 50048
#define KCH 64
#define NCHUNK (D_MODEL / KCH)                            // 2
#define SAH 72    // smem A stride (halfs)
#define SWH 136   // smem W stride (halfs)
#define SMA_HALFS (TILE_M * SAH)                          // 9216
#define SMW_HALFS (KCH * SWH)                             // 8704
#define SWF 132   // epilogue fp32 tile stride (floats)
#define QKV_DSMEM ((2 * SMA_HALFS + 2 * SMW_HALFS) * 2)   // 71680 B

#define SHADOW_NODES 12544      // 1568 blocks x 8 nodes — profiled subset

// ---------------- scratch (static device globals; no runtime alloc) ----------
__device__ __align__(256) float  g_Q  [(size_t)PAD_NODES * D_MODEL];
__device__ __align__(256) __half g_Kh [(size_t)PAD_NODES * D_MODEL];
__device__ __align__(256) __half g_Vh [(size_t)PAD_NODES * D_MODEL];
__device__ __align__(256) __half g_embH[(size_t)PAD_NODES * D_MODEL];
__device__ __align__(256) __half g_WH [3 * D_MODEL * D_MODEL];
__device__ __align__(256) int    g_deg[N_NODES];
__device__ __align__(256) int    g_start[N_NODES + 1];
__device__ __align__(256) int    g_cursor[N_NODES];
__device__ __align__(256) int    g_csr_col[N_EDGES + 16];
__device__ __align__(256) int    g_blk_sum[SCAN_NBLK];
__device__ __align__(256) int    g_blk_off[SCAN_NBLK];
__device__ int g_is64;
__device__ int g_spine_ctr;

// ---------------- cp.async helpers --------------------------------------------
__device__ __forceinline__ uint32_t smem_u32(const void* p) {
    uint32_t a;
    asm("{ .reg .u64 t; cvta.to.shared.u64 t, %1; cvt.u32.u64 %0, t; }"
        : "=r"(a) : "l"(p));
    return a;
}
#define CP16(dst_u32, src_ptr) \
    asm volatile("cp.async.cg.shared.global [%0], [%1], 16;" \
                 :: "r"(dst_u32), "l"(src_ptr))
#define CP_COMMIT()  asm volatile("cp.async.commit_group;" ::: "memory")
#define CP_WAIT1()   asm volatile("cp.async.wait_group 1;" ::: "memory")

// ---------------- edge index handling -----------------------------------------
__device__ __forceinline__ int load_edge(const void* p, int is64, size_t idx) {
    int v;
    if (is64) v = (int)((const long long*)p)[idx];
    else      v = ((const int*)p)[idx];
    v = v < 0 ? 0 : (v >= N_NODES ? N_NODES - 1 : v);
    return v;
}

// ---------------- convert emb + W to fp16 (zero-padded rows) -------------------
__global__ void convert_h_kernel(const float* __restrict__ emb,
                                 const float* __restrict__ Wq,
                                 const float* __restrict__ Wk,
                                 const float* __restrict__ Wv)
{
    const int i = blockIdx.x * blockDim.x + threadIdx.x;
    const int EMB8 = PAD_NODES * (D_MODEL / 8);
    if (i < EMB8) {
        const int row = i >> 4;
        __half2 h[4];
        if (row < N_NODES) {
            const float4 v0 = ((const float4*)emb)[i * 2];
            const float4 v1 = ((const float4*)emb)[i * 2 + 1];
            h[0] = __floats2half2_rn(v0.x, v0.y);
            h[1] = __floats2half2_rn(v0.z, v0.w);
            h[2] = __floats2half2_rn(v1.x, v1.y);
            h[3] = __floats2half2_rn(v1.z, v1.w);
        } else {
            h[0] = h[1] = h[2] = h[3] = __floats2half2_rn(0.f, 0.f);
        }
        ((uint4*)g_embH)[i] = *(uint4*)h;
    } else {
        const int j = i - EMB8;
        if (j < 3 * D_MODEL * D_MODEL / 8) {
            const int mat = j / (D_MODEL * D_MODEL / 8);
            const int e8  = j % (D_MODEL * D_MODEL / 8);
            const float4* src = (const float4*)((mat == 0) ? Wq : (mat == 1) ? Wk : Wv);
            const float4 v0 = src[e8 * 2];
            const float4 v1 = src[e8 * 2 + 1];
            __half2 h[4];
            h[0] = __floats2half2_rn(v0.x, v0.y);
            h[1] = __floats2half2_rn(v0.z, v0.w);
            h[2] = __floats2half2_rn(v1.x, v1.y);
            h[3] = __floats2half2_rn(v1.z, v1.w);
            ((uint4*)g_WH)[j] = *(uint4*)h;
        }
    }
}

// ---------------- CSR 1: zero degrees + detect edge dtype ----------------------
__global__ void init_kernel(const int* __restrict__ raw) {
    const int i = blockIdx.x * blockDim.x + threadIdx.x;
    if (i < N_NODES) g_deg[i] = 0;
    if (blockIdx.x == 0 && threadIdx.x < 32) {
        const int lane = threadIdx.x;
        int acc = 0;
        for (int k = lane; k < 1024; k += 32)
            acc |= raw[2 * k + 1];
#pragma unroll
        for (int o = 16; o > 0; o >>= 1)
            acc |= __shfl_xor_sync(0xffffffffu, acc, o);
        if (lane == 0) g_is64 = (acc == 0) ? 1 : 0;
    }
}

// ---------------- CSR 2: degree count ------------------------------------------
__global__ void degree_kernel(const void* __restrict__ edge_index) {
    int e = blockIdx.x * blockDim.x + threadIdx.x;
    if (e < N_EDGES) {
        const int is64 = g_is64;
        int row = load_edge(edge_index, is64, e);
        atomicAdd(&g_deg[row], 1);
    }
}

// ---------------- CSR 3: block sums + spine scan (last block) ------------------
__global__ void scan_reduce_spine_kernel() {
    __shared__ int wsum[SCAN_BLK / 32];
    __shared__ int sh[256];
    __shared__ int is_last;
    const int tid = threadIdx.x;
    const int i = blockIdx.x * SCAN_BLK + tid;

    int d = (i < N_NODES) ? g_deg[i] : 0;
    int s = d;
#pragma unroll
    for (int o = 16; o > 0; o >>= 1) s += __shfl_xor_sync(0xffffffffu, s, o);
    if ((tid & 31) == 0) wsum[tid >> 5] = s;
    __syncthreads();
    if (tid == 0) {
        int t = 0;
#pragma unroll
        for (int w = 0; w < SCAN_BLK / 32; w++) t += wsum[w];
        g_blk_sum[blockIdx.x] = t;
        __threadfence();
        int tk = atomicAdd(&g_spine_ctr, 1);
        is_last = (tk == SCAN_NBLK - 1) ? 1 : 0;
    }
    __syncthreads();
    if (!is_last) return;

    __threadfence();
    int v = (tid < SCAN_NBLK) ? g_blk_sum[tid] : 0;
    sh[tid] = v;
    __syncthreads();
    for (int off = 1; off < 256; off <<= 1) {
        int u = (tid >= off) ? sh[tid - off] : 0;
        __syncthreads();
        sh[tid] += u;
        __syncthreads();
    }
    if (tid < SCAN_NBLK) g_blk_off[tid] = sh[tid] - v;
    if (tid == 0) {
        g_start[N_NODES] = N_EDGES;
        g_spine_ctr = 0;
    }
}

// ---------------- CSR 4: block-local exclusive scan + spine offset -------------
__global__ void scan_final_kernel() {
    __shared__ int wsum[SCAN_BLK / 32];
    const int tid  = threadIdx.x;
    const int lane = tid & 31;
    const int wid  = tid >> 5;
    const int i = blockIdx.x * SCAN_BLK + tid;

    int d = (i < N_NODES) ? g_deg[i] : 0;
    int inc = d;
#pragma unroll
    for (int o = 1; o < 32; o <<= 1) {
        int u = __shfl_up_sync(0xffffffffu, inc, o);
        if (lane >= o) inc += u;
    }
    if (lane == 31) wsum[wid] = inc;
    __syncthreads();
    if (wid == 0) {
        int w = (lane < SCAN_BLK / 32) ? wsum[lane] : 0;
#pragma unroll
        for (int o = 1; o < SCAN_BLK / 32; o <<= 1) {
            int u = __shfl_up_sync(0xffffffffu, w, o);
            if (lane >= o) w += u;
        }
        if (lane < SCAN_BLK / 32) wsum[lane] = w;
    }
    __syncthreads();
    int base = g_blk_off[blockIdx.x] + (wid > 0 ? wsum[wid - 1] : 0);
    int excl = base + inc - d;
    if (i < N_NODES) {
        g_start[i]  = excl;
        g_cursor[i] = excl;
    }
}

// ---------------- CSR 5: scatter cols into CSR ---------------------------------
__global__ void scatter_kernel(const void* __restrict__ edge_index) {
    int e = blockIdx.x * blockDim.x + threadIdx.x;
    if (e < N_EDGES) {
        const int is64 = g_is64;
        int row = load_edge(edge_index, is64, e);
        int col = load_edge(edge_index, is64, (size_t)N_EDGES + e);
        int idx = atomicAdd(&g_cursor[row], 1);
        if (idx >= 0 && idx < N_EDGES) g_csr_col[idx] = col;
    }
}

// ---------------- QKV GEMM — fp16 HMMA (m16n16k16), cp.async double buffer -----
__global__ __launch_bounds__(256, 2) void qkv_tc_kernel()
{
    extern __shared__ __half dynsmh[];
    __half* const smA0 = dynsmh;
    __half* const smA1 = dynsmh + SMA_HALFS;
    __half* const smW0 = dynsmh + 2 * SMA_HALFS;
    __half* const smW1 = dynsmh + 2 * SMA_HALFS + SMW_HALFS;

    const int tid = threadIdx.x;
    const int wid = tid >> 5;
    const int warp_m = wid >> 1;
    const int warp_n = wid & 1;
    const int mat = blockIdx.y;
    const __half* __restrict__ Wsrc = g_WH + (size_t)mat * D_MODEL * D_MODEL;
    const int row0 = blockIdx.x * TILE_M;

    auto issue = [&](int kc, int buf) {
        __half* sA = buf ? smA1 : smA0;
        __half* sW = buf ? smW1 : smW0;
        const uint32_t dA = smem_u32(sA);
        const uint32_t dW = smem_u32(sW);
#pragma unroll
        for (int j = 0; j < 4; j++) {
            const int c = j * 256 + tid;
            {
                const int r = c >> 3, q = c & 7;
                CP16(dA + r * (SAH * 2) + q * 16,
                     g_embH + (size_t)(row0 + r) * D_MODEL + kc + q * 8);
            }
            {
                const int r = c >> 4, q = c & 15;
                CP16(dW + r * (SWH * 2) + q * 16,
                     Wsrc + (size_t)(kc + r) * D_MODEL + q * 8);
            }
        }
    };

    wmma::fragment<wmma::accumulator, 16, 16, 16, float> c[2][4];
#pragma unroll
    for (int m = 0; m < 2; m++)
#pragma unroll
        for (int n = 0; n < 4; n++)
            wmma::fill_fragment(c[m][n], 0.0f);

    issue(0, 0);
    CP_COMMIT();

    for (int ch = 0; ch < NCHUNK; ch++) {
        const int buf = ch & 1;
        if (ch + 1 < NCHUNK) issue((ch + 1) * KCH, (ch + 1) & 1);
        CP_COMMIT();
        CP_WAIT1();
        __syncthreads();

        __half* sA = buf ? smA1 : smA0;
        __half* sW = buf ? smW1 : smW0;

#pragma unroll
        for (int kk = 0; kk < KCH / 16; kk++) {
            wmma::fragment<wmma::matrix_a, 16, 16, 16, __half, wmma::row_major> a[2];
            wmma::fragment<wmma::matrix_b, 16, 16, 16, __half, wmma::row_major> b[4];
#pragma unroll
            for (int m = 0; m < 2; m++)
                wmma::load_matrix_sync(a[m],
                    sA + (warp_m * 32 + m * 16) * SAH + kk * 16, SAH);
#pragma unroll
            for (int n = 0; n < 4; n++)
                wmma::load_matrix_sync(b[n],
                    sW + (kk * 16) * SWH + warp_n * 64 + n * 16, SWH);
#pragma unroll
            for (int m = 0; m < 2; m++)
#pragma unroll
                for (int n = 0; n < 4; n++)
                    wmma::mma_sync(c[m][n], a[m], b[n], c[m][n]);
        }
        __syncthreads();
    }

    if (mat == 0) {
#pragma unroll
        for (int m = 0; m < 2; m++)
#pragma unroll
            for (int n = 0; n < 4; n++)
                wmma::store_matrix_sync(
                    g_Q + (size_t)(row0 + warp_m * 32 + m * 16) * D_MODEL
                        + warp_n * 64 + n * 16,
                    c[m][n], D_MODEL, wmma::mem_row_major);
    } else {
        float* sT = (float*)dynsmh;
#pragma unroll
        for (int m = 0; m < 2; m++)
#pragma unroll
            for (int n = 0; n < 4; n++)
                wmma::store_matrix_sync(
                    sT + (warp_m * 32 + m * 16) * SWF + warp_n * 64 + n * 16,
                    c[m][n], SWF, wmma::mem_row_major);
        __syncthreads();

        __half* __restrict__ Gh = (mat == 1) ? g_Kh : g_Vh;
#pragma unroll
        for (int j = 0; j < 8; j++) {
            const int e = (j * 256 + tid) * 8;
            const int r = e >> 7, col = e & 127;
            const float* src = sT + r * SWF + col;
            __half2 h[4];
#pragma unroll
            for (int t = 0; t < 4; t++)
                h[t] = __floats2half2_rn(src[2 * t], src[2 * t + 1]);
            *(uint4*)(Gh + (size_t)(row0 + r) * D_MODEL + col) = *(uint4*)h;
        }
    }
}

// ---------------- attn body (R13 form), parameterized for shadow/real ----------
// warp per destination node. 8-edge window per iteration; all window loads
// issued before any score math consumes them.
__device__ __forceinline__ void attn_body(
    int n, int lane, int deg_cap,
    const float* __restrict__ emb,
    const float* __restrict__ ln_scale,
    const float* __restrict__ ln_bias,
    float* __restrict__ out)
{
    const int grp  = lane >> 3;   // 0..3 : edge-in-quad I score
    const int h    = lane & 7;    // 0..7 : head I score
    const int hout = lane >> 2;   // 0..7 : head of my output columns

    const float* qrow = g_Q + (size_t)n * D_MODEL + h * 16;
    float q[16];
#pragma unroll
    for (int t = 0; t < 4; t++) {
        const float4 qq = *(const float4*)(qrow + t * 4);
        q[t * 4 + 0] = qq.x; q[t * 4 + 1] = qq.y;
        q[t * 4 + 2] = qq.z; q[t * 4 + 3] = qq.w;
    }

    float4 acc = make_float4(0.f, 0.f, 0.f, 0.f);
    float norm = 0.f;

    const int s = g_start[n];
    int t = g_start[n + 1];
    // shadow safety: bound loop length (also guards stale-s/new-t races)
    if (t < s) t = s;
    if (t > s + deg_cap) t = s + deg_cap;
    if (t > N_EDGES) t = N_EDGES;

    for (int e = s; e < t; e += 8) {
        int c[8];
#pragma unroll
        for (int j = 0; j < 8; j++)
            c[j] = (e + j < t) ? g_csr_col[e + j] : 0;

        const int colA = c[grp];
        const int colB = c[4 + grp];
        const __half* krA = g_Kh + (size_t)colA * D_MODEL + h * 16;
        const __half* krB = g_Kh + (size_t)colB * D_MODEL + h * 16;
        const uint4 kA0 = *(const uint4*)(krA);
        const uint4 kA1 = *(const uint4*)(krA + 8);
        const uint4 kB0 = *(const uint4*)(krB);
        const uint4 kB1 = *(const uint4*)(krB + 8);

        uint2 vr[8];
#pragma unroll
        for (int j = 0; j < 8; j++)
            vr[j] = *(const uint2*)(g_Vh + (size_t)c[j] * D_MODEL + lane * 4);

        float dA = 0.f, dB = 0.f;
        {
            const __half2* a0 = (const __half2*)&kA0;
            const __half2* a1 = (const __half2*)&kA1;
            const __half2* b0 = (const __half2*)&kB0;
            const __half2* b1 = (const __half2*)&kB1;
#pragma unroll
            for (int p = 0; p < 4; p++) {
                const float2 fa0 = __half22float2(a0[p]);
                const float2 fa1 = __half22float2(a1[p]);
                const float2 fb0 = __half22float2(b0[p]);
                const float2 fb1 = __half22float2(b1[p]);
                dA += q[2 * p] * fa0.x + q[2 * p + 1] * fa0.y
                    + q[8 + 2 * p] * fa1.x + q[9 + 2 * p] * fa1.y;
                dB += q[2 * p] * fb0.x + q[2 * p + 1] * fb0.y
                    + q[8 + 2 * p] * fb1.x + q[9 + 2 * p] * fb1.y;
            }
        }
        dA = fminf(fmaxf(dA, -10.f), 10.f);
        dB = fminf(fmaxf(dB, -10.f), 10.f);
        const float wA = (e + grp     < t) ? __expf(dA) : 0.f;
        const float wB = (e + 4 + grp < t) ? __expf(dB) : 0.f;

        float w8[8];
#pragma unroll
        for (int j = 0; j < 4; j++) {
            w8[j]     = __shfl_sync(0xffffffffu, wA, j * 8 + hout);
            w8[4 + j] = __shfl_sync(0xffffffffu, wB, j * 8 + hout);
        }

#pragma unroll
        for (int j = 0; j < 8; j++) {
            const __half2* v = (const __half2*)&vr[j];
            const float2 v0 = __half22float2(v[0]);
            const float2 v1 = __half22float2(v[1]);
            acc.x += w8[j] * v0.x;
            acc.y += w8[j] * v0.y;
            acc.z += w8[j] * v1.x;
            acc.w += w8[j] * v1.y;
            norm  += w8[j];
        }
    }

    const size_t loff = (size_t)lane * 4;
    const float scale = 1.f / (norm + 1e-8f);
    const float4 e4 = *(const float4*)(emb + (size_t)n * D_MODEL + loff);
    float4 r;
    r.x = acc.x * scale + e4.x;
    r.y = acc.y * scale + e4.y;
    r.z = acc.z * scale + e4.z;
    r.w = acc.w * scale + e4.w;

    float ssum = r.x + r.y + r.z + r.w;
    float ssq  = r.x * r.x + r.y * r.y + r.z * r.z + r.w * r.w;
#pragma unroll
    for (int o = 16; o > 0; o >>= 1) {
        ssum += __shfl_xor_sync(0xffffffffu, ssum, o);
        ssq  += __shfl_xor_sync(0xffffffffu, ssq,  o);
    }
    const float mu  = ssum * (1.f / 128.f);
    const float var = ssq * (1.f / 128.f) - mu * mu;
    const float inv = rsqrtf(var + 1e-6f);

    const float4 sc = *(const float4*)(ln_scale + loff);
    const float4 bi = *(const float4*)(ln_bias + loff);
    float4 o4;
    o4.x = (r.x - mu) * inv * sc.x + bi.x;
    o4.y = (r.y - mu) * inv * sc.y + bi.y;
    o4.z = (r.z - mu) * inv * sc.z + bi.z;
    o4.w = (r.w - mu) * inv * sc.w + bi.w;
    *(float4*)(out + (size_t)n * D_MODEL + loff) = o4;
}

// real attn: all nodes, full degree (cap = N_EDGES, i.e. no cap)
__global__ __launch_bounds__(256) void attn_kernel(
    const float* __restrict__ emb,
    const float* __restrict__ ln_scale,
    const float* __restrict__ ln_bias,
    float* __restrict__ out)
{
    const int n = (blockIdx.x * blockDim.x + threadIdx.x) >> 5;
    const int lane = threadIdx.x & 31;
    if (n >= N_NODES) return;
    attn_body(n, lane, N_EDGES, emb, ln_scale, ln_bias, out);
}

// shadow attn: first SHADOW_NODES nodes on PREVIOUS-replay state, deg capped.
// Output is fully overwritten by the real attn. Exists so ncu (slot 4) can
// profile the attention kernel's true pipe/stall/occupancy behavior.
__global__ __launch_bounds__(256) void attn_shadow_kernel(
    const float* __restrict__ emb,
    const float* __restrict__ ln_scale,
    const float* __restrict__ ln_bias,
    float* __restrict__ out)
{
    const int n = (blockIdx.x * blockDim.x + threadIdx.x) >> 5;
    const int lane = threadIdx.x & 31;
    if (n >= SHADOW_NODES) return;
    attn_body(n, lane, 64, emb, ln_scale, ln_bias, out);
}

// ---------------- launch ------------------------------------------------------
// Submission order puts attn_shadow at slot 4 (the ncu-profiled launch).
extern "C" void kernel_launch(void* const* d_in, const int* in_sizes, int n_in,
                              void* d_out, int out_size)
{
    const float* emb      = (const float*)d_in[0];
    const void*  edge_idx = d_in[1];
    const float* Wq       = (const float*)d_in[2];
    const float* Wk       = (const float*)d_in[3];
    const float* Wv       = (const float*)d_in[4];
    const float* ln_s     = (const float*)d_in[5];
    const float* ln_b     = (const float*)d_in[6];
    float*       out      = (float*)d_out;

    const int CV8 = PAD_NODES * (D_MODEL / 8) + 3 * D_MODEL * D_MODEL / 8;

    cudaFuncSetAttribute(qkv_tc_kernel,
                         cudaFuncAttributeMaxDynamicSharedMemorySize, QKV_DSMEM);

    static cudaStream_t s2 = nullptr;
    static cudaEvent_t  evFork = nullptr, evJoin = nullptr;
    static bool tried = false;
    if (!tried) {
        tried = true;
        if (cudaStreamCreateWithFlags(&s2, cudaStreamNonBlocking) != cudaSuccess)
            s2 = nullptr;
        if (s2) {
            if (cudaEventCreateWithFlags(&evFork, cudaEventDisableTiming) != cudaSuccess ||
                cudaEventCreateWithFlags(&evJoin, cudaEventDisableTiming) != cudaSuccess) {
                s2 = nullptr;
            }
        }
    }

    const int SHADOW_BLOCKS = SHADOW_NODES / 8;    // 1568

    if (s2) {
        cudaEventRecord(evFork, 0);
        cudaStreamWaitEvent(s2, evFork, 0);

        convert_h_kernel<<<(CV8 + 255) / 256, 256>>>(emb, Wq, Wk, Wv);            // 1 (main)
        init_kernel<<<SCAN_NBLK, SCAN_BLK, 0, s2>>>((const int*)edge_idx);        // 2 (s2)
        degree_kernel<<<(N_EDGES + 255) / 256, 256, 0, s2>>>(edge_idx);           // 3 (s2)
        attn_shadow_kernel<<<SHADOW_BLOCKS, 256>>>(emb, ln_s, ln_b, out);         // 4 (main) <- PROFILED
        qkv_tc_kernel<<<dim3(N_TILES, 3), 256, QKV_DSMEM>>>();                    // 5 (main)
        scan_reduce_spine_kernel<<<SCAN_NBLK, SCAN_BLK, 0, s2>>>();               // 6 (s2)
        scan_final_kernel<<<SCAN_NBLK, SCAN_BLK, 0, s2>>>();                      // 7 (s2)
        scatter_kernel<<<(N_EDGES + 255) / 256, 256, 0, s2>>>(edge_idx);          // 8 (s2)
        cudaEventRecord(evJoin, s2);

        cudaStreamWaitEvent(0, evJoin, 0);
        attn_kernel<<<(N_NODES + 7) / 8, 256>>>(emb, ln_s, ln_b, out);            // 9
    } else {
        convert_h_kernel<<<(CV8 + 255) / 256, 256>>>(emb, Wq, Wk, Wv);
        init_kernel<<<SCAN_NBLK, SCAN_BLK>>>((const int*)edge_idx);
        degree_kernel<<<(N_EDGES + 255) / 256, 256>>>(edge_idx);
        attn_shadow_kernel<<<SHADOW_BLOCKS, 256>>>(emb, ln_s, ln_b, out);
        qkv_tc_kernel<<<dim3(N_TILES, 3), 256, QKV_DSMEM>>>();
        scan_reduce_spine_kernel<<<SCAN_NBLK, SCAN_BLK>>>();
        scan_final_kernel<<<SCAN_NBLK, SCAN_BLK>>>();
        scatter_kernel<<<(N_EDGES + 255) / 256, 256>>>(edge_idx);
        attn_kernel<<<(N_NODES + 7) / 8, 256>>>(emb, ln_s, ln_b, out);
    }
}

// round 17
// speedup vs baseline: 1.2364x; 1.2364x over previous
#include <cuda_runtime.h>
#include <cuda_fp16.h>
#include <cstdint>
#include <mma.h>

using namespace nvcuda;

#define N_NODES 50000
#define N_EDGES 800000
#define D_MODEL 128
// heads = 8, head_dim = 16

#define SCAN_BLK 256
#define SCAN_NBLK ((N_NODES + SCAN_BLK - 1) / SCAN_BLK)   // 196

#define TILE_M 128
#define N_TILES ((N_NODES + TILE_M - 1) / TILE_M)         // 391
#define PAD_NODES (N_TILES * TILE_M)                      // 50048
#define KCH 64
#define NCHUNK (D_MODEL / KCH)                            // 2
#define SAH 72    // smem A stride (halfs)
#define SWH 136   // smem W stride (halfs)
#define SMA_HALFS (TILE_M * SAH)                          // 9216
#define SMW_HALFS (KCH * SWH)                             // 8704
#define SWF 132   // epilogue fp32 tile stride (floats)
#define QKV_DSMEM ((2 * SMA_HALFS + 2 * SMW_HALFS) * 2)   // 71680 B

// ---------------- scratch (static device globals; no runtime alloc) ----------
__device__ __align__(256) float  g_Q  [(size_t)PAD_NODES * D_MODEL];
__device__ __align__(256) __half g_Kh [(size_t)PAD_NODES * D_MODEL];
__device__ __align__(256) __half g_Vh [(size_t)PAD_NODES * D_MODEL];
__device__ __align__(256) __half g_embH[(size_t)PAD_NODES * D_MODEL];
__device__ __align__(256) __half g_WH [3 * D_MODEL * D_MODEL];
__device__ __align__(256) int    g_deg[N_NODES];     // invariant: all-zero at kernel_launch entry
__device__ __align__(256) int    g_start[N_NODES + 1];
__device__ __align__(256) int    g_cursor[N_NODES];
__device__ __align__(256) int    g_csr_col[N_EDGES + 16];
__device__ __align__(256) int    g_blk_sum[SCAN_NBLK];
__device__ __align__(256) int    g_blk_off[SCAN_NBLK];
__device__ int g_is64;
__device__ int g_spine_ctr;

// ---------------- cp.async helpers --------------------------------------------
__device__ __forceinline__ uint32_t smem_u32(const void* p) {
    uint32_t a;
    asm("{ .reg .u64 t; cvta.to.shared.u64 t, %1; cvt.u32.u64 %0, t; }"
        : "=r"(a) : "l"(p));
    return a;
}
#define CP16(dst_u32, src_ptr) \
    asm volatile("cp.async.cg.shared.global [%0], [%1], 16;" \
                 :: "r"(dst_u32), "l"(src_ptr))
#define CP_COMMIT()  asm volatile("cp.async.commit_group;" ::: "memory")
#define CP_WAIT1()   asm volatile("cp.async.wait_group 1;" ::: "memory")

// ---------------- edge index handling -----------------------------------------
__device__ __forceinline__ int load_edge(const void* p, int is64, size_t idx) {
    int v;
    if (is64) v = (int)((const long long*)p)[idx];
    else      v = ((const int*)p)[idx];
    v = v < 0 ? 0 : (v >= N_NODES ? N_NODES - 1 : v);
    return v;
}

// ---------------- convert emb + W to fp16 (zero-padded rows) -------------------
__global__ void convert_h_kernel(const float* __restrict__ emb,
                                 const float* __restrict__ Wq,
                                 const float* __restrict__ Wk,
                                 const float* __restrict__ Wv)
{
    const int i = blockIdx.x * blockDim.x + threadIdx.x;
    const int EMB8 = PAD_NODES * (D_MODEL / 8);
    if (i < EMB8) {
        const int row = i >> 4;
        __half2 h[4];
        if (row < N_NODES) {
            const float4 v0 = ((const float4*)emb)[i * 2];
            const float4 v1 = ((const float4*)emb)[i * 2 + 1];
            h[0] = __floats2half2_rn(v0.x, v0.y);
            h[1] = __floats2half2_rn(v0.z, v0.w);
            h[2] = __floats2half2_rn(v1.x, v1.y);
            h[3] = __floats2half2_rn(v1.z, v1.w);
        } else {
            h[0] = h[1] = h[2] = h[3] = __floats2half2_rn(0.f, 0.f);
        }
        ((uint4*)g_embH)[i] = *(uint4*)h;
    } else {
        const int j = i - EMB8;
        if (j < 3 * D_MODEL * D_MODEL / 8) {
            const int mat = j / (D_MODEL * D_MODEL / 8);
            const int e8  = j % (D_MODEL * D_MODEL / 8);
            const float4* src = (const float4*)((mat == 0) ? Wq : (mat == 1) ? Wk : Wv);
            const float4 v0 = src[e8 * 2];
            const float4 v1 = src[e8 * 2 + 1];
            __half2 h[4];
            h[0] = __floats2half2_rn(v0.x, v0.y);
            h[1] = __floats2half2_rn(v0.z, v0.w);
            h[2] = __floats2half2_rn(v1.x, v1.y);
            h[3] = __floats2half2_rn(v1.z, v1.w);
            ((uint4*)g_WH)[j] = *(uint4*)h;
        }
    }
}

// ---------------- CSR 1: detect edge dtype (1 warp) ----------------------------
__global__ void detect_kernel(const int* __restrict__ raw) {
    const int lane = threadIdx.x & 31;
    int acc = 0;
    for (int k = lane; k < 1024; k += 32)
        acc |= raw[2 * k + 1];
#pragma unroll
    for (int o = 16; o > 0; o >>= 1)
        acc |= __shfl_xor_sync(0xffffffffu, acc, o);
    if (lane == 0) g_is64 = (acc == 0) ? 1 : 0;
}

// ---------------- CSR 2: degree count (g_deg is zero on entry) ------------------
__global__ void degree_kernel(const void* __restrict__ edge_index) {
    int e = blockIdx.x * blockDim.x + threadIdx.x;
    if (e < N_EDGES) {
        const int is64 = g_is64;
        int row = load_edge(edge_index, is64, e);
        atomicAdd(&g_deg[row], 1);
    }
}

// ---------------- CSR 3: block sums + spine scan (last block) ------------------
__global__ void scan_reduce_spine_kernel() {
    __shared__ int wsum[SCAN_BLK / 32];
    __shared__ int sh[256];
    __shared__ int is_last;
    const int tid = threadIdx.x;
    const int i = blockIdx.x * SCAN_BLK + tid;

    int d = (i < N_NODES) ? g_deg[i] : 0;
    int s = d;
#pragma unroll
    for (int o = 16; o > 0; o >>= 1) s += __shfl_xor_sync(0xffffffffu, s, o);
    if ((tid & 31) == 0) wsum[tid >> 5] = s;
    __syncthreads();
    if (tid == 0) {
        int t = 0;
#pragma unroll
        for (int w = 0; w < SCAN_BLK / 32; w++) t += wsum[w];
        g_blk_sum[blockIdx.x] = t;
        __threadfence();
        int tk = atomicAdd(&g_spine_ctr, 1);
        is_last = (tk == SCAN_NBLK - 1) ? 1 : 0;
    }
    __syncthreads();
    if (!is_last) return;

    __threadfence();
    int v = (tid < SCAN_NBLK) ? g_blk_sum[tid] : 0;
    sh[tid] = v;
    __syncthreads();
    for (int off = 1; off < 256; off <<= 1) {
        int u = (tid >= off) ? sh[tid - off] : 0;
        __syncthreads();
        sh[tid] += u;
        __syncthreads();
    }
    if (tid < SCAN_NBLK) g_blk_off[tid] = sh[tid] - v;
    if (tid == 0) {
        g_start[N_NODES] = N_EDGES;
        g_spine_ctr = 0;
    }
}

// ---------------- CSR 4: block-local scan + spine offset; re-zero g_deg --------
__global__ void scan_final_kernel() {
    __shared__ int wsum[SCAN_BLK / 32];
    const int tid  = threadIdx.x;
    const int lane = tid & 31;
    const int wid  = tid >> 5;
    const int i = blockIdx.x * SCAN_BLK + tid;

    int d = (i < N_NODES) ? g_deg[i] : 0;
    int inc = d;
#pragma unroll
    for (int o = 1; o < 32; o <<= 1) {
        int u = __shfl_up_sync(0xffffffffu, inc, o);
        if (lane >= o) inc += u;
    }
    if (lane == 31) wsum[wid] = inc;
    __syncthreads();
    if (wid == 0) {
        int w = (lane < SCAN_BLK / 32) ? wsum[lane] : 0;
#pragma unroll
        for (int o = 1; o < SCAN_BLK / 32; o <<= 1) {
            int u = __shfl_up_sync(0xffffffffu, w, o);
            if (lane >= o) w += u;
        }
        if (lane < SCAN_BLK / 32) wsum[lane] = w;
    }
    __syncthreads();
    int base = g_blk_off[blockIdx.x] + (wid > 0 ? wsum[wid - 1] : 0);
    int excl = base + inc - d;
    if (i < N_NODES) {
        g_start[i]  = excl;
        g_cursor[i] = excl;
        g_deg[i]    = 0;     // maintain all-zero invariant for next replay
    }
}

// ---------------- CSR 5: scatter cols into CSR ---------------------------------
__global__ void scatter_kernel(const void* __restrict__ edge_index) {
    int e = blockIdx.x * blockDim.x + threadIdx.x;
    if (e < N_EDGES) {
        const int is64 = g_is64;
        int row = load_edge(edge_index, is64, e);
        int col = load_edge(edge_index, is64, (size_t)N_EDGES + e);
        int idx = atomicAdd(&g_cursor[row], 1);
        if (idx >= 0 && idx < N_EDGES) g_csr_col[idx] = col;
    }
}

// ---------------- QKV GEMM — fp16 HMMA (m16n16k16), cp.async double buffer -----
__global__ __launch_bounds__(256, 2) void qkv_tc_kernel()
{
    extern __shared__ __half dynsmh[];
    __half* const smA0 = dynsmh;
    __half* const smA1 = dynsmh + SMA_HALFS;
    __half* const smW0 = dynsmh + 2 * SMA_HALFS;
    __half* const smW1 = dynsmh + 2 * SMA_HALFS + SMW_HALFS;

    const int tid = threadIdx.x;
    const int wid = tid >> 5;
    const int warp_m = wid >> 1;
    const int warp_n = wid & 1;
    const int mat = blockIdx.y;
    const __half* __restrict__ Wsrc = g_WH + (size_t)mat * D_MODEL * D_MODEL;
    const int row0 = blockIdx.x * TILE_M;

    auto issue = [&](int kc, int buf) {
        __half* sA = buf ? smA1 : smA0;
        __half* sW = buf ? smW1 : smW0;
        const uint32_t dA = smem_u32(sA);
        const uint32_t dW = smem_u32(sW);
#pragma unroll
        for (int j = 0; j < 4; j++) {
            const int c = j * 256 + tid;
            {
                const int r = c >> 3, q = c & 7;
                CP16(dA + r * (SAH * 2) + q * 16,
                     g_embH + (size_t)(row0 + r) * D_MODEL + kc + q * 8);
            }
            {
                const int r = c >> 4, q = c & 15;
                CP16(dW + r * (SWH * 2) + q * 16,
                     Wsrc + (size_t)(kc + r) * D_MODEL + q * 8);
            }
        }
    };

    wmma::fragment<wmma::accumulator, 16, 16, 16, float> c[2][4];
#pragma unroll
    for (int m = 0; m < 2; m++)
#pragma unroll
        for (int n = 0; n < 4; n++)
            wmma::fill_fragment(c[m][n], 0.0f);

    issue(0, 0);
    CP_COMMIT();

    for (int ch = 0; ch < NCHUNK; ch++) {
        const int buf = ch & 1;
        if (ch + 1 < NCHUNK) issue((ch + 1) * KCH, (ch + 1) & 1);
        CP_COMMIT();
        CP_WAIT1();
        __syncthreads();

        __half* sA = buf ? smA1 : smA0;
        __half* sW = buf ? smW1 : smW0;

#pragma unroll
        for (int kk = 0; kk < KCH / 16; kk++) {
            wmma::fragment<wmma::matrix_a, 16, 16, 16, __half, wmma::row_major> a[2];
            wmma::fragment<wmma::matrix_b, 16, 16, 16, __half, wmma::row_major> b[4];
#pragma unroll
            for (int m = 0; m < 2; m++)
                wmma::load_matrix_sync(a[m],
                    sA + (warp_m * 32 + m * 16) * SAH + kk * 16, SAH);
#pragma unroll
            for (int n = 0; n < 4; n++)
                wmma::load_matrix_sync(b[n],
                    sW + (kk * 16) * SWH + warp_n * 64 + n * 16, SWH);
#pragma unroll
            for (int m = 0; m < 2; m++)
#pragma unroll
                for (int n = 0; n < 4; n++)
                    wmma::mma_sync(c[m][n], a[m], b[n], c[m][n]);
        }
        __syncthreads();
    }

    if (mat == 0) {
#pragma unroll
        for (int m = 0; m < 2; m++)
#pragma unroll
            for (int n = 0; n < 4; n++)
                wmma::store_matrix_sync(
                    g_Q + (size_t)(row0 + warp_m * 32 + m * 16) * D_MODEL
                        + warp_n * 64 + n * 16,
                    c[m][n], D_MODEL, wmma::mem_row_major);
    } else {
        float* sT = (float*)dynsmh;
#pragma unroll
        for (int m = 0; m < 2; m++)
#pragma unroll
            for (int n = 0; n < 4; n++)
                wmma::store_matrix_sync(
                    sT + (warp_m * 32 + m * 16) * SWF + warp_n * 64 + n * 16,
                    c[m][n], SWF, wmma::mem_row_major);
        __syncthreads();

        __half* __restrict__ Gh = (mat == 1) ? g_Kh : g_Vh;
#pragma unroll
        for (int j = 0; j < 8; j++) {
            const int e = (j * 256 + tid) * 8;
            const int r = e >> 7, col = e & 127;
            const float* src = sT + r * SWF + col;
            __half2 h[4];
#pragma unroll
            for (int t = 0; t < 4; t++)
                h[t] = __floats2half2_rn(src[2 * t], src[2 * t + 1]);
            *(uint4*)(Gh + (size_t)(row0 + r) * D_MODEL + col) = *(uint4*)h;
        }
    }
}

// ---------------- attention + aggregate + residual + LayerNorm -----------------
// warp per destination node; 8-edge window per iteration (R13 body).
// 128-thread blocks with min 8 CTAs/SM (caps regs at 64) -> ~50% occupancy;
// shadow profile showed latency-bound at 37.5% occ with all pipes idle.
__global__ __launch_bounds__(128, 8) void attn_kernel(
    const float* __restrict__ emb,
    const float* __restrict__ ln_scale,
    const float* __restrict__ ln_bias,
    float* __restrict__ out)
{
    const int n = (blockIdx.x * blockDim.x + threadIdx.x) >> 5;
    const int lane = threadIdx.x & 31;
    if (n >= N_NODES) return;

    const int grp  = lane >> 3;   // 0..3 : edge-in-quad I score
    const int h    = lane & 7;    // 0..7 : head I score
    const int hout = lane >> 2;   // 0..7 : head of my output columns

    const float* qrow = g_Q + (size_t)n * D_MODEL + h * 16;
    float q[16];
#pragma unroll
    for (int t = 0; t < 4; t++) {
        const float4 qq = *(const float4*)(qrow + t * 4);
        q[t * 4 + 0] = qq.x; q[t * 4 + 1] = qq.y;
        q[t * 4 + 2] = qq.z; q[t * 4 + 3] = qq.w;
    }

    float4 acc = make_float4(0.f, 0.f, 0.f, 0.f);
    float norm = 0.f;

    const int s = g_start[n];
    const int t = g_start[n + 1];

    for (int e = s; e < t; e += 8) {
        int c[8];
#pragma unroll
        for (int j = 0; j < 8; j++)
            c[j] = (e + j < t) ? g_csr_col[e + j] : 0;

        const int colA = c[grp];
        const int colB = c[4 + grp];
        const __half* krA = g_Kh + (size_t)colA * D_MODEL + h * 16;
        const __half* krB = g_Kh + (size_t)colB * D_MODEL + h * 16;
        const uint4 kA0 = *(const uint4*)(krA);
        const uint4 kA1 = *(const uint4*)(krA + 8);
        const uint4 kB0 = *(const uint4*)(krB);
        const uint4 kB1 = *(const uint4*)(krB + 8);

        uint2 vr[8];
#pragma unroll
        for (int j = 0; j < 8; j++)
            vr[j] = *(const uint2*)(g_Vh + (size_t)c[j] * D_MODEL + lane * 4);

        float dA = 0.f, dB = 0.f;
        {
            const __half2* a0 = (const __half2*)&kA0;
            const __half2* a1 = (const __half2*)&kA1;
            const __half2* b0 = (const __half2*)&kB0;
            const __half2* b1 = (const __half2*)&kB1;
#pragma unroll
            for (int p = 0; p < 4; p++) {
                const float2 fa0 = __half22float2(a0[p]);
                const float2 fa1 = __half22float2(a1[p]);
                const float2 fb0 = __half22float2(b0[p]);
                const float2 fb1 = __half22float2(b1[p]);
                dA += q[2 * p] * fa0.x + q[2 * p + 1] * fa0.y
                    + q[8 + 2 * p] * fa1.x + q[9 + 2 * p] * fa1.y;
                dB += q[2 * p] * fb0.x + q[2 * p + 1] * fb0.y
                    + q[8 + 2 * p] * fb1.x + q[9 + 2 * p] * fb1.y;
            }
        }
        dA = fminf(fmaxf(dA, -10.f), 10.f);
        dB = fminf(fmaxf(dB, -10.f), 10.f);
        const float wA = (e + grp     < t) ? __expf(dA) : 0.f;
        const float wB = (e + 4 + grp < t) ? __expf(dB) : 0.f;

        float w8[8];
#pragma unroll
        for (int j = 0; j < 4; j++) {
            w8[j]     = __shfl_sync(0xffffffffu, wA, j * 8 + hout);
            w8[4 + j] = __shfl_sync(0xffffffffu, wB, j * 8 + hout);
        }

#pragma unroll
        for (int j = 0; j < 8; j++) {
            const __half2* v = (const __half2*)&vr[j];
            const float2 v0 = __half22float2(v[0]);
            const float2 v1 = __half22float2(v[1]);
            acc.x += w8[j] * v0.x;
            acc.y += w8[j] * v0.y;
            acc.z += w8[j] * v1.x;
            acc.w += w8[j] * v1.y;
            norm  += w8[j];
        }
    }

    const size_t loff = (size_t)lane * 4;
    const float scale = 1.f / (norm + 1e-8f);
    const float4 e4 = *(const float4*)(emb + (size_t)n * D_MODEL + loff);
    float4 r;
    r.x = acc.x * scale + e4.x;
    r.y = acc.y * scale + e4.y;
    r.z = acc.z * scale + e4.z;
    r.w = acc.w * scale + e4.w;

    float ssum = r.x + r.y + r.z + r.w;
    float ssq  = r.x * r.x + r.y * r.y + r.z * r.z + r.w * r.w;
#pragma unroll
    for (int o = 16; o > 0; o >>= 1) {
        ssum += __shfl_xor_sync(0xffffffffu, ssum, o);
        ssq  += __shfl_xor_sync(0xffffffffu, ssq,  o);
    }
    const float mu  = ssum * (1.f / 128.f);
    const float var = ssq * (1.f / 128.f) - mu * mu;
    const float inv = rsqrtf(var + 1e-6f);

    const float4 sc = *(const float4*)(ln_scale + loff);
    const float4 bi = *(const float4*)(ln_bias + loff);
    float4 o4;
    o4.x = (r.x - mu) * inv * sc.x + bi.x;
    o4.y = (r.y - mu) * inv * sc.y + bi.y;
    o4.z = (r.z - mu) * inv * sc.z + bi.z;
    o4.w = (r.w - mu) * inv * sc.w + bi.w;
    *(float4*)(out + (size_t)n * D_MODEL + loff) = o4;
}

// ---------------- launch ------------------------------------------------------
// main: convert -> qkv ; s2: detect -> degree -> spine -> final -> scatter.
// qkv is the 4th-submitted launch (ncu-profiled slot).
extern "C" void kernel_launch(void* const* d_in, const int* in_sizes, int n_in,
                              void* d_out, int out_size)
{
    const float* emb      = (const float*)d_in[0];
    const void*  edge_idx = d_in[1];
    const float* Wq       = (const float*)d_in[2];
    const float* Wk       = (const float*)d_in[3];
    const float* Wv       = (const float*)d_in[4];
    const float* ln_s     = (const float*)d_in[5];
    const float* ln_b     = (const float*)d_in[6];
    float*       out      = (float*)d_out;

    const int CV8 = PAD_NODES * (D_MODEL / 8) + 3 * D_MODEL * D_MODEL / 8;

    cudaFuncSetAttribute(qkv_tc_kernel,
                         cudaFuncAttributeMaxDynamicSharedMemorySize, QKV_DSMEM);

    static cudaStream_t s2 = nullptr;
    static cudaEvent_t  evFork = nullptr, evJoin = nullptr;
    static bool tried = false;
    if (!tried) {
        tried = true;
        if (cudaStreamCreateWithFlags(&s2, cudaStreamNonBlocking) != cudaSuccess)
            s2 = nullptr;
        if (s2) {
            if (cudaEventCreateWithFlags(&evFork, cudaEventDisableTiming) != cudaSuccess ||
                cudaEventCreateWithFlags(&evJoin, cudaEventDisableTiming) != cudaSuccess) {
                s2 = nullptr;
            }
        }
    }

    const int ATTN_BLOCKS = (N_NODES + 3) / 4;    // 128-thread blocks, 4 nodes each

    if (s2) {
        cudaEventRecord(evFork, 0);
        cudaStreamWaitEvent(s2, evFork, 0);

        convert_h_kernel<<<(CV8 + 255) / 256, 256>>>(emb, Wq, Wk, Wv);       // 1 (main)
        detect_kernel<<<1, 32, 0, s2>>>((const int*)edge_idx);               // 2 (s2)
        degree_kernel<<<(N_EDGES + 255) / 256, 256, 0, s2>>>(edge_idx);      // 3 (s2)
        qkv_tc_kernel<<<dim3(N_TILES, 3), 256, QKV_DSMEM>>>();               // 4 (main) <- profiled
        scan_reduce_spine_kernel<<<SCAN_NBLK, SCAN_BLK, 0, s2>>>();          // 5 (s2)
        scan_final_kernel<<<SCAN_NBLK, SCAN_BLK, 0, s2>>>();                 // 6 (s2)
        scatter_kernel<<<(N_EDGES + 255) / 256, 256, 0, s2>>>(edge_idx);     // 7 (s2)
        cudaEventRecord(evJoin, s2);

        cudaStreamWaitEvent(0, evJoin, 0);
        attn_kernel<<<ATTN_BLOCKS, 128>>>(emb, ln_s, ln_b, out);             // 8
    } else {
        convert_h_kernel<<<(CV8 + 255) / 256, 256>>>(emb, Wq, Wk, Wv);
        detect_kernel<<<1, 32>>>((const int*)edge_idx);
        degree_kernel<<<(N_EDGES + 255) / 256, 256>>>(edge_idx);
        scan_reduce_spine_kernel<<<SCAN_NBLK, SCAN_BLK>>>();
        qkv_tc_kernel<<<dim3(N_TILES, 3), 256, QKV_DSMEM>>>();
        scan_final_kernel<<<SCAN_NBLK, SCAN_BLK>>>();
        scatter_kernel<<<(N_EDGES + 255) / 256, 256>>>(edge_idx);
        attn_kernel<<<ATTN_BLOCKS, 128>>>(emb, ln_s, ln_b, out);
    }
}